// round 1
// baseline (speedup 1.0000x reference)
#include <cuda_runtime.h>
#include <math.h>

#define Bb 8
#define Nn 2048
#define Ee 32
#define Hc 128
#define Sc 256
#define Tt 12
#define NEL (Bb*Ee*Nn)
#define ALPHA 0.05f
#define EPSV 1e-5f
#define SPLIT 4
#define VT 128
#define WCH 64

// ---------------- device scratch (no runtime allocation) ----------------
__device__ float g_x[NEL];
__device__ float g_xacc[NEL];
__device__ float g_h1[NEL];
__device__ float g_h2[NEL];
__device__ float g_hid[Bb*Hc*Nn];
__device__ float g_hid2[Bb*Hc*Nn];
__device__ float g_skip[Bb*Sc*Nn];
__device__ float g_u[SPLIT][NEL];
__device__ float g_rs_s[Nn];
__device__ float g_rs_d[Bb*Nn];
__device__ float g_cs_d[Bb*Nn];
__device__ float g_stats[Bb*2];

struct Srcs { const float* p[8]; };

// ---------------- helpers ----------------
__device__ __forceinline__ float blockReduceSum(float v) {
    __shared__ float sh[32];
    int lane = threadIdx.x & 31, wid = threadIdx.x >> 5;
    #pragma unroll
    for (int o = 16; o; o >>= 1) v += __shfl_down_sync(0xffffffffu, v, o);
    __syncthreads();
    if (lane == 0) sh[wid] = v;
    __syncthreads();
    int nw = blockDim.x >> 5;
    v = (threadIdx.x < nw) ? sh[threadIdx.x] : 0.f;
    if (wid == 0) {
        #pragma unroll
        for (int o = 16; o; o >>= 1) v += __shfl_down_sync(0xffffffffu, v, o);
    }
    return v;
}

__global__ void copyk(float* __restrict__ dst, const float* __restrict__ src, int n) {
    int i = blockIdx.x * 256 + threadIdx.x;
    if (i < n) dst[i] = src[i];
}

// ---------------- graph degree sums ----------------
__global__ void rowsum_static(const float* __restrict__ S) {
    int v = blockIdx.x;
    float s = 0.f;
    for (int w = threadIdx.x; w < Nn; w += 256) s += S[(size_t)v * Nn + w];
    s = blockReduceSum(s);
    if (threadIdx.x == 0) g_rs_s[v] = s + 1.0f;
}

__global__ void rowsum_dy(const float* __restrict__ A) {
    int b = blockIdx.y, v = blockIdx.x;
    const float* row = A + ((size_t)b * Nn + v) * Nn;
    float s = 0.f;
    for (int w = threadIdx.x; w < Nn; w += 256) s += row[w];
    s = blockReduceSum(s);
    if (threadIdx.x == 0) g_rs_d[b * Nn + v] = s + 1.0f;
}

__global__ void colsum_dy(const float* __restrict__ A) {
    int b = blockIdx.y;
    int v = blockIdx.x * 256 + threadIdx.x;
    const float* Ab = A + (size_t)b * Nn * Nn;
    float s = 0.f;
    #pragma unroll 4
    for (int w = 0; w < Nn; w++) s += Ab[(size_t)w * Nn + v];
    g_cs_d[b * Nn + v] = s + 1.0f;
}

// ---------------- graph SpMM (raw adjacency, normalization folded later) ----
// out_partial[sp][b,c,v] = sum_{w in split sp} A[v,w] (or A[w,v]) * h[b,c,w]
// Tile: 128 v x 32 c per block, W chunk 64. 256 threads, thread = 4v x 4c.
template <bool TRANS>
__global__ void spmm_k(const float* __restrict__ A, size_t aBStride,
                       const float* __restrict__ h) {
    __shared__ float As[VT * 68];          // non-trans layout [v][j] pitch 68 (>= 64*128 for trans)
    __shared__ float Hs[WCH * 36];         // [j][c] pitch 36

    const int tid  = threadIdx.x;
    const int warp = tid >> 5, lane = tid & 31;
    const int vg4  = lane >> 3, cg = lane & 7;
    const int v0l  = warp * 16 + vg4 * 4;  // local v base (4 rows)
    const int cb   = cg * 4;               // c base (4 cols)

    const int vt = blockIdx.x;             // 0..15
    const int b  = blockIdx.y;             // 0..7
    const int sp = blockIdx.z;             // 0..SPLIT-1
    const int v0 = vt * VT;

    const float* Ab = A + (size_t)b * aBStride;
    const float* hb = h + (size_t)b * Ee * Nn;

    float acc[4][4];
    #pragma unroll
    for (int q = 0; q < 4; q++)
        #pragma unroll
        for (int u = 0; u < 4; u++) acc[q][u] = 0.f;

    const int wSeg = Nn / SPLIT;           // 512
    const int wBase = sp * wSeg;

    for (int wc = 0; wc < wSeg / WCH; wc++) {
        const int w0 = wBase + wc * WCH;
        // --- stage A tile ---
        if (TRANS) {
            // As[j*128 + i] = A[b, w0+j, v0+i]   (read A^T as [w][v], rows contiguous)
            for (int t = tid; t < 2048; t += 256) {
                int j = t >> 5, i4 = t & 31;
                float4 val = *(const float4*)&Ab[(size_t)(w0 + j) * Nn + v0 + i4 * 4];
                *(float4*)&As[j * 128 + i4 * 4] = val;
            }
        } else {
            // As[i*68 + j] = A[b, v0+i, w0+j]
            for (int t = tid; t < 2048; t += 256) {
                int i = t >> 4, j4 = t & 15;
                float4 val = *(const float4*)&Ab[(size_t)(v0 + i) * Nn + w0 + j4 * 4];
                *(float4*)&As[i * 68 + j4 * 4] = val;
            }
        }
        // --- stage H tile: Hs[j*36 + c] = h[b,c,w0+j] ---
        for (int t = tid; t < 512; t += 256) {
            int c = t >> 4, j4 = t & 15;
            float4 val = *(const float4*)&hb[(size_t)c * Nn + w0 + j4 * 4];
            int j = j4 * 4;
            Hs[(j + 0) * 36 + c] = val.x;
            Hs[(j + 1) * 36 + c] = val.y;
            Hs[(j + 2) * 36 + c] = val.z;
            Hs[(j + 3) * 36 + c] = val.w;
        }
        __syncthreads();
        // --- compute ---
        #pragma unroll 16
        for (int j = 0; j < WCH; j++) {
            float4 hv = *(const float4*)&Hs[j * 36 + cb];
            float ha[4] = {hv.x, hv.y, hv.z, hv.w};
            float aa[4];
            if (TRANS) {
                float4 av = *(const float4*)&As[j * 128 + v0l];
                aa[0] = av.x; aa[1] = av.y; aa[2] = av.z; aa[3] = av.w;
            } else {
                aa[0] = As[(v0l + 0) * 68 + j];
                aa[1] = As[(v0l + 1) * 68 + j];
                aa[2] = As[(v0l + 2) * 68 + j];
                aa[3] = As[(v0l + 3) * 68 + j];
            }
            #pragma unroll
            for (int q = 0; q < 4; q++)
                #pragma unroll
                for (int u = 0; u < 4; u++) acc[q][u] = fmaf(ha[q], aa[u], acc[q][u]);
        }
        __syncthreads();
    }
    // --- write partials ---
    #pragma unroll
    for (int q = 0; q < 4; q++) {
        int c = cb + q;
        float4 r = make_float4(acc[q][0], acc[q][1], acc[q][2], acc[q][3]);
        *(float4*)&g_u[sp][((size_t)b * Ee + c) * Nn + v0 + v0l] = r;
    }
}

// h_out = alpha*x + (1-alpha) * (sum_partials + h_prev) / den
__global__ void hop_combine(const float* __restrict__ hprev, float* __restrict__ hout,
                            const float* __restrict__ den, int denB) {
    int i = blockIdx.x * 256 + threadIdx.x;
    if (i >= NEL) return;
    int v = i & (Nn - 1);
    int b = i / (Ee * Nn);
    float s = g_u[0][i] + g_u[1][i] + g_u[2][i] + g_u[3][i] + hprev[i];
    float hn = s / den[denB * b + v];
    hout[i] = ALPHA * g_x[i] + (1.0f - ALPHA) * hn;
}

// ---------------- generic 1x1 conv (channel-mix GEMM) ----------------
// out[b,m,n] (+)= sum_c W[m,c]*in[c,(b,n)] + bias[m]
__global__ void conv1x1_k(Srcs srcs, int inBStride,
                          const float* __restrict__ W, const float* __restrict__ bias,
                          int M, int K, float* __restrict__ out, int outBStride, int accFlag) {
    __shared__ float Ws[16 * 68];
    __shared__ float Ins[16 * 68];
    const int tid = threadIdx.x;
    const int tx = tid & 15, ty = tid >> 4;
    const int col0 = blockIdx.x * 64;
    const int b = col0 / Nn, n0 = col0 % Nn;
    const int m0 = blockIdx.y * 64;

    float acc[4][4];
    #pragma unroll
    for (int u = 0; u < 4; u++)
        #pragma unroll
        for (int q = 0; q < 4; q++) acc[u][q] = 0.f;

    for (int k0 = 0; k0 < K; k0 += 16) {
        for (int t = tid; t < 1024; t += 256) {
            int m = t >> 4, kk = t & 15;
            Ws[kk * 68 + m] = (m0 + m < M) ? W[(size_t)(m0 + m) * K + k0 + kk] : 0.f;
        }
        for (int t = tid; t < 1024; t += 256) {
            int kk = t >> 6, n = t & 63;
            int c = k0 + kk;
            Ins[kk * 68 + n] = srcs.p[c >> 5][(size_t)b * inBStride + (size_t)(c & 31) * Nn + n0 + n];
        }
        __syncthreads();
        #pragma unroll
        for (int kk = 0; kk < 16; kk++) {
            float4 wv = *(const float4*)&Ws[kk * 68 + ty * 4];
            float4 iv = *(const float4*)&Ins[kk * 68 + tx * 4];
            float wa[4] = {wv.x, wv.y, wv.z, wv.w};
            float ia[4] = {iv.x, iv.y, iv.z, iv.w};
            #pragma unroll
            for (int u = 0; u < 4; u++)
                #pragma unroll
                for (int q = 0; q < 4; q++) acc[u][q] = fmaf(wa[u], ia[q], acc[u][q]);
        }
        __syncthreads();
    }
    #pragma unroll
    for (int u = 0; u < 4; u++) {
        int m = m0 + ty * 4 + u;
        if (m >= M) break;
        float bm = bias[m];
        float4 r = make_float4(acc[u][0] + bm, acc[u][1] + bm, acc[u][2] + bm, acc[u][3] + bm);
        float* dst = &out[(size_t)b * outBStride + (size_t)m * Nn + n0 + tx * 4];
        if (accFlag) {
            float4 o = *(float4*)dst;
            r.x += o.x; r.y += o.y; r.z += o.z; r.w += o.w;
        }
        *(float4*)dst = r;
    }
}

// ---------------- gated TCN unit: tanh(Wf in + bf) * sigmoid(Wg in + bg) ------
__global__ void gated_conv_k(Srcs srcs, int inBStride,
                             const float* __restrict__ Wf, const float* __restrict__ bf,
                             const float* __restrict__ Wg, const float* __restrict__ bg,
                             float* __restrict__ out) {
    __shared__ float Wfs[16 * 68];
    __shared__ float Wgs[16 * 68];
    __shared__ float Ins[16 * 68];
    const int tid = threadIdx.x;
    const int tx = tid & 15, ty = tid >> 4;
    const int col0 = blockIdx.x * 64;
    const int b = col0 / Nn, n0 = col0 % Nn;
    const int m0 = blockIdx.y * 64;

    float accF[4][4], accG[4][4];
    #pragma unroll
    for (int u = 0; u < 4; u++)
        #pragma unroll
        for (int q = 0; q < 4; q++) { accF[u][q] = 0.f; accG[u][q] = 0.f; }

    for (int k0 = 0; k0 < Hc; k0 += 16) {
        for (int t = tid; t < 1024; t += 256) {
            int m = t >> 4, kk = t & 15;
            Wfs[kk * 68 + m] = Wf[(size_t)(m0 + m) * Hc + k0 + kk];
            Wgs[kk * 68 + m] = Wg[(size_t)(m0 + m) * Hc + k0 + kk];
        }
        for (int t = tid; t < 1024; t += 256) {
            int kk = t >> 6, n = t & 63;
            int c = k0 + kk;
            Ins[kk * 68 + n] = srcs.p[c >> 5][(size_t)b * inBStride + (size_t)(c & 31) * Nn + n0 + n];
        }
        __syncthreads();
        #pragma unroll
        for (int kk = 0; kk < 16; kk++) {
            float4 fv = *(const float4*)&Wfs[kk * 68 + ty * 4];
            float4 gv = *(const float4*)&Wgs[kk * 68 + ty * 4];
            float4 iv = *(const float4*)&Ins[kk * 68 + tx * 4];
            float fa[4] = {fv.x, fv.y, fv.z, fv.w};
            float ga[4] = {gv.x, gv.y, gv.z, gv.w};
            float ia[4] = {iv.x, iv.y, iv.z, iv.w};
            #pragma unroll
            for (int u = 0; u < 4; u++)
                #pragma unroll
                for (int q = 0; q < 4; q++) {
                    accF[u][q] = fmaf(fa[u], ia[q], accF[u][q]);
                    accG[u][q] = fmaf(ga[u], ia[q], accG[u][q]);
                }
        }
        __syncthreads();
    }
    #pragma unroll
    for (int u = 0; u < 4; u++) {
        int m = m0 + ty * 4 + u;
        float bfm = bf[m], bgm = bg[m];
        float4 r;
        float f, s;
        f = tanhf(accF[u][0] + bfm); s = 1.f / (1.f + expf(-(accG[u][0] + bgm))); r.x = f * s;
        f = tanhf(accF[u][1] + bfm); s = 1.f / (1.f + expf(-(accG[u][1] + bgm))); r.y = f * s;
        f = tanhf(accF[u][2] + bfm); s = 1.f / (1.f + expf(-(accG[u][2] + bgm))); r.z = f * s;
        f = tanhf(accF[u][3] + bfm); s = 1.f / (1.f + expf(-(accG[u][3] + bgm))); r.w = f * s;
        *(float4*)&out[(size_t)b * Hc * Nn + (size_t)m * Nn + n0 + tx * 4] = r;
    }
}

// ---------------- layernorm ----------------
__global__ void ln_stats_k() {
    int b = blockIdx.x;
    const float* xp = g_xacc + (size_t)b * Ee * Nn;
    float s = 0.f, s2 = 0.f;
    for (int i = threadIdx.x; i < Ee * Nn; i += blockDim.x) {
        float v = xp[i];
        s += v; s2 += v * v;
    }
    float ts = blockReduceSum(s);
    float ts2 = blockReduceSum(s2);
    if (threadIdx.x == 0) {
        float inv = 1.0f / (Ee * Nn);
        float mu = ts * inv;
        g_stats[b * 2] = mu;
        g_stats[b * 2 + 1] = ts2 * inv - mu * mu;
    }
}

__global__ void ln_apply_k(const float* __restrict__ w, const float* __restrict__ bparm) {
    int i = blockIdx.x * 256 + threadIdx.x;
    if (i >= NEL) return;
    int b = i / (Ee * Nn);
    int cn = i % (Ee * Nn);
    float mu = g_stats[b * 2];
    float var = g_stats[b * 2 + 1];
    float val = (g_xacc[i] - mu) * rsqrtf(var + EPSV) * w[cn] + bparm[cn];
    g_x[i] = fmaxf(val, 0.f);
}

// ---------------- host orchestration ----------------
extern "C" void kernel_launch(void* const* d_in, const int* in_sizes, int n_in,
                              void* d_out, int out_size) {
    (void)in_sizes; (void)n_in; (void)out_size;
    const float* in_x  = (const float*)d_in[0];
    const float* dyG   = (const float*)d_in[1];
    const float* stG   = (const float*)d_in[2];
    const float* spE   = (const float*)d_in[3];
    const float* tdE   = (const float*)d_in[4];
    const float* twE   = (const float*)d_in[5];
    const float* encWf = (const float*)d_in[6];
    const float* encbf = (const float*)d_in[7];
    const float* encWg = (const float*)d_in[8];
    const float* encbg = (const float*)d_in[9];
    const float* skW   = (const float*)d_in[10];
    const float* skb   = (const float*)d_in[11];
    const float* nw    = (const float*)d_in[12];
    const float* nb    = (const float*)d_in[13];
    const float* gW[3] = {(const float*)d_in[14], (const float*)d_in[16], (const float*)d_in[18]};
    const float* gb[3] = {(const float*)d_in[15], (const float*)d_in[17], (const float*)d_in[19]};
    const float* seW   = (const float*)d_in[20];
    const float* seb   = (const float*)d_in[21];
    const float* eW    = (const float*)d_in[22];
    const float* eb    = (const float*)d_in[23];
    float* outp = (float*)d_out;

    float *px, *pxacc, *ph1, *ph2, *phid, *phid2, *pskip, *prss, *prsd, *pcsd;
    cudaGetSymbolAddress((void**)&px,    g_x);
    cudaGetSymbolAddress((void**)&pxacc, g_xacc);
    cudaGetSymbolAddress((void**)&ph1,   g_h1);
    cudaGetSymbolAddress((void**)&ph2,   g_h2);
    cudaGetSymbolAddress((void**)&phid,  g_hid);
    cudaGetSymbolAddress((void**)&phid2, g_hid2);
    cudaGetSymbolAddress((void**)&pskip, g_skip);
    cudaGetSymbolAddress((void**)&prss,  g_rs_s);
    cudaGetSymbolAddress((void**)&prsd,  g_rs_d);
    cudaGetSymbolAddress((void**)&pcsd,  g_cs_d);

    // x <- input; degree sums (input-only, deterministic each call)
    copyk<<<NEL / 256, 256>>>(px, in_x, NEL);
    rowsum_static<<<Nn, 256>>>(stG);
    rowsum_dy<<<dim3(Nn, Bb), 256>>>(dyG);
    colsum_dy<<<dim3(Nn / 256, Bb), 256>>>(dyG);

    const dim3 convGrid(Bb * Nn / 64, 1);
    for (int i = 0; i < 3; i++) {
        // ---- TCN chain ----
        Srcs s1; s1.p[0] = px; s1.p[1] = spE; s1.p[2] = tdE; s1.p[3] = twE;
        gated_conv_k<<<dim3(Bb * Nn / 64, 2), 256>>>(s1, Ee * Nn,
            encWf + (size_t)(i * 2 + 0) * Hc * Hc, encbf + (i * 2 + 0) * Hc,
            encWg + (size_t)(i * 2 + 0) * Hc * Hc, encbg + (i * 2 + 0) * Hc, phid);
        Srcs s2; for (int s = 0; s < 4; s++) s2.p[s] = phid + (size_t)s * 32 * Nn;
        gated_conv_k<<<dim3(Bb * Nn / 64, 2), 256>>>(s2, Hc * Nn,
            encWf + (size_t)(i * 2 + 1) * Hc * Hc, encbf + (i * 2 + 1) * Hc,
            encWg + (size_t)(i * 2 + 1) * Hc * Hc, encbg + (i * 2 + 1) * Hc, phid2);
        // ---- skip += skip_W @ hidden ----
        Srcs s3; for (int s = 0; s < 4; s++) s3.p[s] = phid2 + (size_t)s * 32 * Nn;
        conv1x1_k<<<dim3(Bb * Nn / 64, 4), 256>>>(s3, Hc * Nn,
            skW + (size_t)i * Sc * Hc, skb + i * Sc, Sc, Hc, pskip, Sc * Nn, i > 0);
        // ---- mixprops: xacc starts at residual, each mlp accumulates ----
        copyk<<<NEL / 256, 256>>>(pxacc, px, NEL);
        for (int g = 0; g < 3; g++) {
            const float* A = (g == 0) ? stG : dyG;
            size_t abst = (g == 0) ? 0 : (size_t)Nn * Nn;
            const float* den = (g == 0) ? prss : (g == 1 ? prsd : pcsd);
            int denB = (g == 0) ? 0 : Nn;
            bool tr = (g == 2);
            // hop 1
            if (tr) spmm_k<true ><<<dim3(16, Bb, SPLIT), 256>>>(A, abst, px);
            else    spmm_k<false><<<dim3(16, Bb, SPLIT), 256>>>(A, abst, px);
            hop_combine<<<NEL / 256, 256>>>(px, ph1, den, denB);
            // hop 2
            if (tr) spmm_k<true ><<<dim3(16, Bb, SPLIT), 256>>>(A, abst, ph1);
            else    spmm_k<false><<<dim3(16, Bb, SPLIT), 256>>>(A, abst, ph1);
            hop_combine<<<NEL / 256, 256>>>(ph1, ph2, den, denB);
            // mlp on concat [x, h1, h2] -> accumulate into xacc
            Srcs sm; sm.p[0] = px; sm.p[1] = ph1; sm.p[2] = ph2;
            conv1x1_k<<<convGrid, 256>>>(sm, Ee * Nn,
                gW[g] + (size_t)i * Ee * 96, gb[g] + i * Ee, Ee, 96, pxacc, Ee * Nn, 1);
        }
        // ---- layernorm + relu -> new x ----
        ln_stats_k<<<Bb, 1024>>>();
        ln_apply_k<<<NEL / 256, 256>>>(nw + (size_t)i * Ee * Nn, nb + (size_t)i * Ee * Nn);
    }
    // ---- skip end + output ----
    Srcs se; se.p[0] = px;
    conv1x1_k<<<dim3(Bb * Nn / 64, 4), 256>>>(se, Ee * Nn, seW, seb, Sc, Ee, pskip, Sc * Nn, 1);
    Srcs send; for (int s = 0; s < 8; s++) send.p[s] = pskip + (size_t)s * 32 * Nn;
    conv1x1_k<<<convGrid, 256>>>(send, Sc * Nn, eW, eb, Tt, Sc, outp, Tt * Nn, 0);
}

// round 2
// speedup vs baseline: 1.1188x; 1.1188x over previous
#include <cuda_runtime.h>
#include <math.h>

#define Bb 8
#define Nn 2048
#define Ee 32
#define Hc 128
#define Sc 256
#define Tt 12
#define NEL (Bb*Ee*Nn)
#define ALPHA 0.05f
#define EPSV 1e-5f
#define SPLIT 4
#define VT 128
#define WCH 64
#define CRS 8

typedef unsigned long long u64;

// ---------------- packed fp32x2 helpers (Blackwell FFMA2) ----------------
__device__ __forceinline__ u64 splat2(float a) {
    u64 d; asm("mov.b64 %0, {%1, %1};" : "=l"(d) : "f"(a)); return d;
}
__device__ __forceinline__ void upk2(u64 v, float& lo, float& hi) {
    asm("mov.b64 {%0, %1}, %2;" : "=f"(lo), "=f"(hi) : "l"(v));
}
__device__ __forceinline__ u64 fma2(u64 a, u64 b, u64 c) {
    u64 d; asm("fma.rn.f32x2 %0, %1, %2, %3;" : "=l"(d) : "l"(a), "l"(b), "l"(c)); return d;
}

// ---------------- device scratch (no runtime allocation) ----------------
__device__ float g_x[NEL];
__device__ float g_xacc[NEL];
__device__ float g_h1[NEL];
__device__ float g_h2[NEL];
__device__ float g_hid[Bb*Hc*Nn];
__device__ float g_hid2[Bb*Hc*Nn];
__device__ float g_skip[Bb*Sc*Nn];
__device__ float g_u[SPLIT][NEL];
__device__ float g_rs_s[Nn];
__device__ float g_rs_d[Bb*Nn];
__device__ float g_cs_d[Bb*Nn];
__device__ float g_csp[CRS][Bb*Nn];
__device__ float g_stats[Bb*2];

struct Srcs { const float* p[8]; };

// ---------------- helpers ----------------
__device__ __forceinline__ float blockReduceSum(float v) {
    __shared__ float sh[32];
    int lane = threadIdx.x & 31, wid = threadIdx.x >> 5;
    #pragma unroll
    for (int o = 16; o; o >>= 1) v += __shfl_down_sync(0xffffffffu, v, o);
    __syncthreads();
    if (lane == 0) sh[wid] = v;
    __syncthreads();
    int nw = blockDim.x >> 5;
    v = (threadIdx.x < nw) ? sh[threadIdx.x] : 0.f;
    if (wid == 0) {
        #pragma unroll
        for (int o = 16; o; o >>= 1) v += __shfl_down_sync(0xffffffffu, v, o);
    }
    return v;
}

__global__ void copyk(float* __restrict__ dst, const float* __restrict__ src, int n) {
    int i = blockIdx.x * 256 + threadIdx.x;
    if (i < n) dst[i] = src[i];
}

// ---------------- graph degree sums ----------------
__global__ void rowsum_static(const float* __restrict__ S) {
    int v = blockIdx.x;
    float s = 0.f;
    for (int w = threadIdx.x; w < Nn; w += 256) s += S[(size_t)v * Nn + w];
    s = blockReduceSum(s);
    if (threadIdx.x == 0) g_rs_s[v] = s + 1.0f;
}

__global__ void rowsum_dy(const float* __restrict__ A) {
    int b = blockIdx.y, v = blockIdx.x;
    const float* row = A + ((size_t)b * Nn + v) * Nn;
    float s = 0.f;
    for (int w = threadIdx.x; w < Nn; w += 256) s += row[w];
    s = blockReduceSum(s);
    if (threadIdx.x == 0) g_rs_d[b * Nn + v] = s + 1.0f;
}

// coalesced, row-split column sums: block covers 256 consecutive columns,
// z-split over row range. 512 blocks, float rows read fully coalesced.
__global__ void colsum_dy(const float* __restrict__ A) {
    int b = blockIdx.y, z = blockIdx.z;
    int c = blockIdx.x * 256 + threadIdx.x;
    const float* Ab = A + (size_t)b * Nn * Nn + (size_t)(z * (Nn / CRS)) * Nn + c;
    float s = 0.f;
    #pragma unroll 8
    for (int r = 0; r < Nn / CRS; r++) s += Ab[(size_t)r * Nn];
    g_csp[z][b * Nn + c] = s;
}

__global__ void colsum_fin() {
    int i = blockIdx.x * 256 + threadIdx.x;
    float s = 1.0f;
    #pragma unroll
    for (int z = 0; z < CRS; z++) s += g_csp[z][i];
    g_cs_d[i] = s;
}

// ---------------- graph SpMM (raw adjacency, normalization folded later) ----
// out_partial[sp][b,c,v] = sum_{w in split sp} A[v,w] (or A[w,v]) * h[b,c,w]
// Tile: 128 v x 32 c per block, W chunk 64. 256 threads, thread = 4v x 4c.
// Accumulators packed over c (fma.rn.f32x2).
template <bool TRANS>
__global__ void spmm_k(const float* __restrict__ A, size_t aBStride,
                       const float* __restrict__ h) {
    __shared__ float As[VT * 68];          // non-trans layout [v][j] pitch 68; trans [j][v] pitch 128
    __shared__ float Hs[WCH * 36];         // [j][c] pitch 36

    const int tid  = threadIdx.x;
    const int warp = tid >> 5, lane = tid & 31;
    const int vg4  = lane >> 3, cg = lane & 7;
    const int v0l  = warp * 16 + vg4 * 4;  // local v base (4 rows)
    const int cb   = cg * 4;               // c base (4 cols)

    const int vt = blockIdx.x;             // 0..15
    const int b  = blockIdx.y;             // 0..7
    const int sp = blockIdx.z;             // 0..SPLIT-1
    const int v0 = vt * VT;

    const float* Ab = A + (size_t)b * aBStride;
    const float* hb = h + (size_t)b * Ee * Nn;

    u64 accP[2][4] = {};                   // [c-pair][v]

    const int wSeg = Nn / SPLIT;           // 512
    const int wBase = sp * wSeg;

    for (int wc = 0; wc < wSeg / WCH; wc++) {
        const int w0 = wBase + wc * WCH;
        // --- stage A tile ---
        if (TRANS) {
            for (int t = tid; t < 2048; t += 256) {
                int j = t >> 5, i4 = t & 31;
                float4 val = *(const float4*)&Ab[(size_t)(w0 + j) * Nn + v0 + i4 * 4];
                *(float4*)&As[j * 128 + i4 * 4] = val;
            }
        } else {
            for (int t = tid; t < 2048; t += 256) {
                int i = t >> 4, j4 = t & 15;
                float4 val = *(const float4*)&Ab[(size_t)(v0 + i) * Nn + w0 + j4 * 4];
                *(float4*)&As[i * 68 + j4 * 4] = val;
            }
        }
        // --- stage H tile: Hs[j*36 + c] = h[b,c,w0+j] ---
        for (int t = tid; t < 512; t += 256) {
            int c = t >> 4, j4 = t & 15;
            float4 val = *(const float4*)&hb[(size_t)c * Nn + w0 + j4 * 4];
            int j = j4 * 4;
            Hs[(j + 0) * 36 + c] = val.x;
            Hs[(j + 1) * 36 + c] = val.y;
            Hs[(j + 2) * 36 + c] = val.z;
            Hs[(j + 3) * 36 + c] = val.w;
        }
        __syncthreads();
        // --- compute ---
        #pragma unroll 8
        for (int j = 0; j < WCH; j++) {
            u64 hp0 = *(const u64*)&Hs[j * 36 + cb];
            u64 hp1 = *(const u64*)&Hs[j * 36 + cb + 2];
            float aa[4];
            if (TRANS) {
                float4 av = *(const float4*)&As[j * 128 + v0l];
                aa[0] = av.x; aa[1] = av.y; aa[2] = av.z; aa[3] = av.w;
            } else {
                aa[0] = As[(v0l + 0) * 68 + j];
                aa[1] = As[(v0l + 1) * 68 + j];
                aa[2] = As[(v0l + 2) * 68 + j];
                aa[3] = As[(v0l + 3) * 68 + j];
            }
            #pragma unroll
            for (int u = 0; u < 4; u++) {
                u64 av2 = splat2(aa[u]);
                accP[0][u] = fma2(hp0, av2, accP[0][u]);
                accP[1][u] = fma2(hp1, av2, accP[1][u]);
            }
        }
        __syncthreads();
    }
    // --- write partials ---
    #pragma unroll
    for (int p = 0; p < 2; p++) {
        float4 rlo, rhi;
        upk2(accP[p][0], rlo.x, rhi.x);
        upk2(accP[p][1], rlo.y, rhi.y);
        upk2(accP[p][2], rlo.z, rhi.z);
        upk2(accP[p][3], rlo.w, rhi.w);
        int c = cb + 2 * p;
        *(float4*)&g_u[sp][((size_t)b * Ee + c) * Nn + v0 + v0l] = rlo;
        *(float4*)&g_u[sp][((size_t)b * Ee + c + 1) * Nn + v0 + v0l] = rhi;
    }
}

// h_out = alpha*x + (1-alpha) * (sum_partials + h_prev) / den
__global__ void hop_combine(const float* __restrict__ hprev, float* __restrict__ hout,
                            const float* __restrict__ den, int denB) {
    int i = blockIdx.x * 256 + threadIdx.x;
    if (i >= NEL) return;
    int v = i & (Nn - 1);
    int b = i / (Ee * Nn);
    float s = g_u[0][i] + g_u[1][i] + g_u[2][i] + g_u[3][i] + hprev[i];
    float hn = s / den[denB * b + v];
    hout[i] = ALPHA * g_x[i] + (1.0f - ALPHA) * hn;
}

// ---------------- generic 1x1 conv (channel-mix GEMM), f32x2 packed ----------
// out[b,m,n] (+)= sum_c W[m,c]*in[c,(b,n)] + bias[m]
__global__ void conv1x1_k(Srcs srcs, int inBStride,
                          const float* __restrict__ W, const float* __restrict__ bias,
                          int M, int K, float* __restrict__ out, int outBStride, int accFlag) {
    __shared__ float Ws[16 * 68];
    __shared__ float Ins[16 * 68];
    const int tid = threadIdx.x;
    const int tx = tid & 15, ty = tid >> 4;
    const int col0 = blockIdx.x * 64;
    const int b = col0 / Nn, n0 = col0 % Nn;
    const int m0 = blockIdx.y * 64;

    u64 accP[4][2] = {};                   // [m][n-pair]

    for (int k0 = 0; k0 < K; k0 += 16) {
        for (int t = tid; t < 1024; t += 256) {
            int m = t >> 4, kk = t & 15;
            Ws[kk * 68 + m] = (m0 + m < M) ? W[(size_t)(m0 + m) * K + k0 + kk] : 0.f;
        }
        for (int t = tid; t < 1024; t += 256) {
            int kk = t >> 6, n = t & 63;
            int c = k0 + kk;
            Ins[kk * 68 + n] = srcs.p[c >> 5][(size_t)b * inBStride + (size_t)(c & 31) * Nn + n0 + n];
        }
        __syncthreads();
        #pragma unroll
        for (int kk = 0; kk < 16; kk++) {
            float4 wv = *(const float4*)&Ws[kk * 68 + ty * 4];
            u64 ip0 = *(const u64*)&Ins[kk * 68 + tx * 4];
            u64 ip1 = *(const u64*)&Ins[kk * 68 + tx * 4 + 2];
            float wa[4] = {wv.x, wv.y, wv.z, wv.w};
            #pragma unroll
            for (int u = 0; u < 4; u++) {
                u64 wp = splat2(wa[u]);
                accP[u][0] = fma2(wp, ip0, accP[u][0]);
                accP[u][1] = fma2(wp, ip1, accP[u][1]);
            }
        }
        __syncthreads();
    }
    #pragma unroll
    for (int u = 0; u < 4; u++) {
        int m = m0 + ty * 4 + u;
        if (m >= M) break;
        float bm = bias[m];
        float4 r;
        upk2(accP[u][0], r.x, r.y);
        upk2(accP[u][1], r.z, r.w);
        r.x += bm; r.y += bm; r.z += bm; r.w += bm;
        float* dst = &out[(size_t)b * outBStride + (size_t)m * Nn + n0 + tx * 4];
        if (accFlag) {
            float4 o = *(float4*)dst;
            r.x += o.x; r.y += o.y; r.z += o.z; r.w += o.w;
        }
        *(float4*)dst = r;
    }
}

// ---------------- gated TCN unit: tanh(Wf in + bf) * sigmoid(Wg in + bg) ------
__global__ void gated_conv_k(Srcs srcs, int inBStride,
                             const float* __restrict__ Wf, const float* __restrict__ bf,
                             const float* __restrict__ Wg, const float* __restrict__ bg,
                             float* __restrict__ out) {
    __shared__ float Wfs[16 * 68];
    __shared__ float Wgs[16 * 68];
    __shared__ float Ins[16 * 68];
    const int tid = threadIdx.x;
    const int tx = tid & 15, ty = tid >> 4;
    const int col0 = blockIdx.x * 64;
    const int b = col0 / Nn, n0 = col0 % Nn;
    const int m0 = blockIdx.y * 64;

    u64 accF[4][2] = {};
    u64 accG[4][2] = {};

    for (int k0 = 0; k0 < Hc; k0 += 16) {
        for (int t = tid; t < 1024; t += 256) {
            int m = t >> 4, kk = t & 15;
            Wfs[kk * 68 + m] = Wf[(size_t)(m0 + m) * Hc + k0 + kk];
            Wgs[kk * 68 + m] = Wg[(size_t)(m0 + m) * Hc + k0 + kk];
        }
        for (int t = tid; t < 1024; t += 256) {
            int kk = t >> 6, n = t & 63;
            int c = k0 + kk;
            Ins[kk * 68 + n] = srcs.p[c >> 5][(size_t)b * inBStride + (size_t)(c & 31) * Nn + n0 + n];
        }
        __syncthreads();
        #pragma unroll
        for (int kk = 0; kk < 16; kk++) {
            float4 fv = *(const float4*)&Wfs[kk * 68 + ty * 4];
            float4 gv = *(const float4*)&Wgs[kk * 68 + ty * 4];
            u64 ip0 = *(const u64*)&Ins[kk * 68 + tx * 4];
            u64 ip1 = *(const u64*)&Ins[kk * 68 + tx * 4 + 2];
            float fa[4] = {fv.x, fv.y, fv.z, fv.w};
            float ga[4] = {gv.x, gv.y, gv.z, gv.w};
            #pragma unroll
            for (int u = 0; u < 4; u++) {
                u64 fp = splat2(fa[u]);
                u64 gp = splat2(ga[u]);
                accF[u][0] = fma2(fp, ip0, accF[u][0]);
                accF[u][1] = fma2(fp, ip1, accF[u][1]);
                accG[u][0] = fma2(gp, ip0, accG[u][0]);
                accG[u][1] = fma2(gp, ip1, accG[u][1]);
            }
        }
        __syncthreads();
    }
    #pragma unroll
    for (int u = 0; u < 4; u++) {
        int m = m0 + ty * 4 + u;
        float bfm = bf[m], bgm = bg[m];
        float ff[4], gg[4];
        upk2(accF[u][0], ff[0], ff[1]);
        upk2(accF[u][1], ff[2], ff[3]);
        upk2(accG[u][0], gg[0], gg[1]);
        upk2(accG[u][1], gg[2], gg[3]);
        float4 r;
        float f, s;
        f = tanhf(ff[0] + bfm); s = 1.f / (1.f + expf(-(gg[0] + bgm))); r.x = f * s;
        f = tanhf(ff[1] + bfm); s = 1.f / (1.f + expf(-(gg[1] + bgm))); r.y = f * s;
        f = tanhf(ff[2] + bfm); s = 1.f / (1.f + expf(-(gg[2] + bgm))); r.z = f * s;
        f = tanhf(ff[3] + bfm); s = 1.f / (1.f + expf(-(gg[3] + bgm))); r.w = f * s;
        *(float4*)&out[(size_t)b * Hc * Nn + (size_t)m * Nn + n0 + tx * 4] = r;
    }
}

// ---------------- layernorm ----------------
__global__ void ln_stats_k() {
    int b = blockIdx.x;
    const float* xp = g_xacc + (size_t)b * Ee * Nn;
    float s = 0.f, s2 = 0.f;
    for (int i = threadIdx.x; i < Ee * Nn; i += blockDim.x) {
        float v = xp[i];
        s += v; s2 += v * v;
    }
    float ts = blockReduceSum(s);
    float ts2 = blockReduceSum(s2);
    if (threadIdx.x == 0) {
        float inv = 1.0f / (Ee * Nn);
        float mu = ts * inv;
        g_stats[b * 2] = mu;
        g_stats[b * 2 + 1] = ts2 * inv - mu * mu;
    }
}

__global__ void ln_apply_k(const float* __restrict__ w, const float* __restrict__ bparm) {
    int i = blockIdx.x * 256 + threadIdx.x;
    if (i >= NEL) return;
    int b = i / (Ee * Nn);
    int cn = i % (Ee * Nn);
    float mu = g_stats[b * 2];
    float var = g_stats[b * 2 + 1];
    float val = (g_xacc[i] - mu) * rsqrtf(var + EPSV) * w[cn] + bparm[cn];
    g_x[i] = fmaxf(val, 0.f);
}

// ---------------- host orchestration ----------------
extern "C" void kernel_launch(void* const* d_in, const int* in_sizes, int n_in,
                              void* d_out, int out_size) {
    (void)in_sizes; (void)n_in; (void)out_size;
    const float* in_x  = (const float*)d_in[0];
    const float* dyG   = (const float*)d_in[1];
    const float* stG   = (const float*)d_in[2];
    const float* spE   = (const float*)d_in[3];
    const float* tdE   = (const float*)d_in[4];
    const float* twE   = (const float*)d_in[5];
    const float* encWf = (const float*)d_in[6];
    const float* encbf = (const float*)d_in[7];
    const float* encWg = (const float*)d_in[8];
    const float* encbg = (const float*)d_in[9];
    const float* skW   = (const float*)d_in[10];
    const float* skb   = (const float*)d_in[11];
    const float* nw    = (const float*)d_in[12];
    const float* nb    = (const float*)d_in[13];
    const float* gW[3] = {(const float*)d_in[14], (const float*)d_in[16], (const float*)d_in[18]};
    const float* gb[3] = {(const float*)d_in[15], (const float*)d_in[17], (const float*)d_in[19]};
    const float* seW   = (const float*)d_in[20];
    const float* seb   = (const float*)d_in[21];
    const float* eW    = (const float*)d_in[22];
    const float* eb    = (const float*)d_in[23];
    float* outp = (float*)d_out;

    float *px, *pxacc, *ph1, *ph2, *phid, *phid2, *pskip, *prss, *prsd, *pcsd;
    cudaGetSymbolAddress((void**)&px,    g_x);
    cudaGetSymbolAddress((void**)&pxacc, g_xacc);
    cudaGetSymbolAddress((void**)&ph1,   g_h1);
    cudaGetSymbolAddress((void**)&ph2,   g_h2);
    cudaGetSymbolAddress((void**)&phid,  g_hid);
    cudaGetSymbolAddress((void**)&phid2, g_hid2);
    cudaGetSymbolAddress((void**)&pskip, g_skip);
    cudaGetSymbolAddress((void**)&prss,  g_rs_s);
    cudaGetSymbolAddress((void**)&prsd,  g_rs_d);
    cudaGetSymbolAddress((void**)&pcsd,  g_cs_d);

    // x <- input; degree sums (input-only, deterministic each call)
    copyk<<<NEL / 256, 256>>>(px, in_x, NEL);
    rowsum_static<<<Nn, 256>>>(stG);
    rowsum_dy<<<dim3(Nn, Bb), 256>>>(dyG);
    colsum_dy<<<dim3(Nn / 256, Bb, CRS), 256>>>(dyG);
    colsum_fin<<<Bb * Nn / 256, 256>>>();

    const dim3 convGrid(Bb * Nn / 64, 1);
    for (int i = 0; i < 3; i++) {
        // ---- TCN chain ----
        Srcs s1; s1.p[0] = px; s1.p[1] = spE; s1.p[2] = tdE; s1.p[3] = twE;
        gated_conv_k<<<dim3(Bb * Nn / 64, 2), 256>>>(s1, Ee * Nn,
            encWf + (size_t)(i * 2 + 0) * Hc * Hc, encbf + (i * 2 + 0) * Hc,
            encWg + (size_t)(i * 2 + 0) * Hc * Hc, encbg + (i * 2 + 0) * Hc, phid);
        Srcs s2; for (int s = 0; s < 4; s++) s2.p[s] = phid + (size_t)s * 32 * Nn;
        gated_conv_k<<<dim3(Bb * Nn / 64, 2), 256>>>(s2, Hc * Nn,
            encWf + (size_t)(i * 2 + 1) * Hc * Hc, encbf + (i * 2 + 1) * Hc,
            encWg + (size_t)(i * 2 + 1) * Hc * Hc, encbg + (i * 2 + 1) * Hc, phid2);
        // ---- skip += skip_W @ hidden ----
        Srcs s3; for (int s = 0; s < 4; s++) s3.p[s] = phid2 + (size_t)s * 32 * Nn;
        conv1x1_k<<<dim3(Bb * Nn / 64, 4), 256>>>(s3, Hc * Nn,
            skW + (size_t)i * Sc * Hc, skb + i * Sc, Sc, Hc, pskip, Sc * Nn, i > 0);
        // ---- mixprops: xacc starts at residual, each mlp accumulates ----
        copyk<<<NEL / 256, 256>>>(pxacc, px, NEL);
        for (int g = 0; g < 3; g++) {
            const float* A = (g == 0) ? stG : dyG;
            size_t abst = (g == 0) ? 0 : (size_t)Nn * Nn;
            const float* den = (g == 0) ? prss : (g == 1 ? prsd : pcsd);
            int denB = (g == 0) ? 0 : Nn;
            bool tr = (g == 2);
            // hop 1
            if (tr) spmm_k<true ><<<dim3(16, Bb, SPLIT), 256>>>(A, abst, px);
            else    spmm_k<false><<<dim3(16, Bb, SPLIT), 256>>>(A, abst, px);
            hop_combine<<<NEL / 256, 256>>>(px, ph1, den, denB);
            // hop 2
            if (tr) spmm_k<true ><<<dim3(16, Bb, SPLIT), 256>>>(A, abst, ph1);
            else    spmm_k<false><<<dim3(16, Bb, SPLIT), 256>>>(A, abst, ph1);
            hop_combine<<<NEL / 256, 256>>>(ph1, ph2, den, denB);
            // mlp on concat [x, h1, h2] -> accumulate into xacc
            Srcs sm; sm.p[0] = px; sm.p[1] = ph1; sm.p[2] = ph2;
            conv1x1_k<<<convGrid, 256>>>(sm, Ee * Nn,
                gW[g] + (size_t)i * Ee * 96, gb[g] + i * Ee, Ee, 96, pxacc, Ee * Nn, 1);
        }
        // ---- layernorm + relu -> new x ----
        ln_stats_k<<<Bb, 1024>>>();
        ln_apply_k<<<NEL / 256, 256>>>(nw + (size_t)i * Ee * Nn, nb + (size_t)i * Ee * Nn);
    }
    // ---- skip end + output ----
    Srcs se; se.p[0] = px;
    conv1x1_k<<<dim3(Bb * Nn / 64, 4), 256>>>(se, Ee * Nn, seW, seb, Sc, Ee, pskip, Sc * Nn, 1);
    Srcs send; for (int s = 0; s < 8; s++) send.p[s] = pskip + (size_t)s * 32 * Nn;
    conv1x1_k<<<convGrid, 256>>>(send, Sc * Nn, eW, eb, Tt, Sc, outp, Tt * Nn, 0);
}

// round 3
// speedup vs baseline: 1.1973x; 1.0701x over previous
#include <cuda_runtime.h>
#include <math.h>

#define Bb 8
#define Nn 2048
#define Ee 32
#define Hc 128
#define Sc 256
#define Tt 12
#define NEL (Bb*Ee*Nn)
#define ALPHA 0.05f
#define EPSV 1e-5f
#define SPLIT 4
#define WCH 32
#define APITCH 132
#define CRS 8

typedef unsigned long long u64;

// ---------------- packed fp32x2 helpers (Blackwell FFMA2) ----------------
__device__ __forceinline__ u64 splat2(float a) {
    u64 d; asm("mov.b64 %0, {%1, %1};" : "=l"(d) : "f"(a)); return d;
}
__device__ __forceinline__ void upk2(u64 v, float& lo, float& hi) {
    asm("mov.b64 {%0, %1}, %2;" : "=f"(lo), "=f"(hi) : "l"(v));
}
__device__ __forceinline__ u64 fma2(u64 a, u64 b, u64 c) {
    u64 d; asm("fma.rn.f32x2 %0, %1, %2, %3;" : "=l"(d) : "l"(a), "l"(b), "l"(c)); return d;
}

// ---------------- device scratch (no runtime allocation) ----------------
__device__ float g_x[NEL];
__device__ float g_xacc[NEL];
__device__ float g_h1[NEL];
__device__ float g_h2[NEL];
__device__ float g_hid[Bb*Hc*Nn];
__device__ float g_hid2[Bb*Hc*Nn];
__device__ float g_skip[Bb*Sc*Nn];
__device__ float g_u[SPLIT][NEL];
__device__ float g_rs_s[Nn];
__device__ float g_rs_d[Bb*Nn];
__device__ float g_cs_d[Bb*Nn];
__device__ float g_csp[CRS][Bb*Nn];
__device__ float g_stats[Bb*2];

struct Srcs { const float* p[8]; };

// ---------------- helpers ----------------
__device__ __forceinline__ float blockReduceSum(float v) {
    __shared__ float sh[32];
    int lane = threadIdx.x & 31, wid = threadIdx.x >> 5;
    #pragma unroll
    for (int o = 16; o; o >>= 1) v += __shfl_down_sync(0xffffffffu, v, o);
    __syncthreads();
    if (lane == 0) sh[wid] = v;
    __syncthreads();
    int nw = blockDim.x >> 5;
    v = (threadIdx.x < nw) ? sh[threadIdx.x] : 0.f;
    if (wid == 0) {
        #pragma unroll
        for (int o = 16; o; o >>= 1) v += __shfl_down_sync(0xffffffffu, v, o);
    }
    return v;
}

__global__ void copyk(float* __restrict__ dst, const float* __restrict__ src, int n) {
    int i = blockIdx.x * 256 + threadIdx.x;
    if (i < n) dst[i] = src[i];
}

// ---------------- graph degree sums ----------------
__global__ void rowsum_static(const float* __restrict__ S) {
    int v = blockIdx.x;
    float s = 0.f;
    for (int w = threadIdx.x; w < Nn; w += 256) s += S[(size_t)v * Nn + w];
    s = blockReduceSum(s);
    if (threadIdx.x == 0) g_rs_s[v] = s + 1.0f;
}

__global__ void rowsum_dy(const float* __restrict__ A) {
    int b = blockIdx.y, v = blockIdx.x;
    const float* row = A + ((size_t)b * Nn + v) * Nn;
    float s = 0.f;
    for (int w = threadIdx.x; w < Nn; w += 256) s += row[w];
    s = blockReduceSum(s);
    if (threadIdx.x == 0) g_rs_d[b * Nn + v] = s + 1.0f;
}

__global__ void colsum_dy(const float* __restrict__ A) {
    int b = blockIdx.y, z = blockIdx.z;
    int c = blockIdx.x * 256 + threadIdx.x;
    const float* Ab = A + (size_t)b * Nn * Nn + (size_t)(z * (Nn / CRS)) * Nn + c;
    float s = 0.f;
    #pragma unroll 8
    for (int r = 0; r < Nn / CRS; r++) s += Ab[(size_t)r * Nn];
    g_csp[z][b * Nn + c] = s;
}

__global__ void colsum_fin() {
    int i = blockIdx.x * 256 + threadIdx.x;
    float s = 1.0f;
    #pragma unroll
    for (int z = 0; z < CRS; z++) s += g_csp[z][i];
    g_cs_d[i] = s;
}

// ---------------- graph SpMM ----------------
// out_partial[sp][b,c,v] = sum_{w in split sp} A[v,w] (or A[w,v]) * h[b,c,w]
// Block: 128 threads, tile 128v x 32c, w chunk 32.
// Per-thread 8v x 4c; accumulators packed in f32x2 pairs over v;
// A staged transposed [j][v] so v-pairs load as LDS.64 (no splat on A).
template <bool TRANS>
__global__ void __launch_bounds__(128) spmm_k(const float* __restrict__ A, size_t aBStride,
                                              const float* __restrict__ h) {
    __shared__ float As[WCH * APITCH];     // [j][v], pitch 132
    __shared__ float Hs[WCH * 36];         // [j][c], pitch 36

    const int tid = threadIdx.x;
    const int vth = tid >> 3;              // 0..15
    const int cth = tid & 7;               // 0..7
    const int v0l = vth * 8;
    const int cb  = cth * 4;

    const int vt = blockIdx.x;             // 0..15
    const int b  = blockIdx.y;             // 0..7
    const int sp = blockIdx.z;             // 0..SPLIT-1
    const int v0 = vt * 128;

    const float* Ab = A + (size_t)b * aBStride;
    const float* hb = h + (size_t)b * Ee * Nn;

    u64 acc[4][4] = {};                    // [v-pair][c]

    const int wSeg = Nn / SPLIT;           // 512
    const int wBase = sp * wSeg;

    for (int wc = 0; wc < wSeg / WCH; wc++) {
        const int w0 = wBase + wc * WCH;
        // --- stage A into [j][v] ---
        if (TRANS) {
            // As[j][i] = A[w0+j, v0+i]; rows contiguous in v -> float4 direct
            #pragma unroll
            for (int t = tid; t < 1024; t += 128) {
                int j = t >> 5, i4 = t & 31;
                float4 val = *(const float4*)&Ab[(size_t)(w0 + j) * Nn + v0 + i4 * 4];
                *(float4*)&As[j * APITCH + i4 * 4] = val;
            }
        } else {
            // As[j][i] = A[v0+i, w0+j]; read row i (contiguous in j), transpose-store
            #pragma unroll
            for (int t = tid; t < 1024; t += 128) {
                int i = t >> 3, j4 = t & 7;
                float4 val = *(const float4*)&Ab[(size_t)(v0 + i) * Nn + w0 + j4 * 4];
                int j = j4 * 4;
                As[(j + 0) * APITCH + i] = val.x;
                As[(j + 1) * APITCH + i] = val.y;
                As[(j + 2) * APITCH + i] = val.z;
                As[(j + 3) * APITCH + i] = val.w;
            }
        }
        // --- stage H: Hs[j][c] = h[b,c,w0+j] ---
        #pragma unroll
        for (int t = tid; t < 256; t += 128) {
            int c = t >> 3, j4 = t & 7;
            float4 val = *(const float4*)&hb[(size_t)c * Nn + w0 + j4 * 4];
            int j = j4 * 4;
            Hs[(j + 0) * 36 + c] = val.x;
            Hs[(j + 1) * 36 + c] = val.y;
            Hs[(j + 2) * 36 + c] = val.z;
            Hs[(j + 3) * 36 + c] = val.w;
        }
        __syncthreads();
        // --- compute ---
        #pragma unroll 8
        for (int j = 0; j < WCH; j++) {
            const float* Aj = &As[j * APITCH + v0l];
            u64 a0 = *(const u64*)(Aj + 0);
            u64 a1 = *(const u64*)(Aj + 2);
            u64 a2 = *(const u64*)(Aj + 4);
            u64 a3 = *(const u64*)(Aj + 6);
            const float* Hj = &Hs[j * 36 + cb];
            #pragma unroll
            for (int q = 0; q < 4; q++) {
                u64 hs = splat2(Hj[q]);
                acc[0][q] = fma2(a0, hs, acc[0][q]);
                acc[1][q] = fma2(a1, hs, acc[1][q]);
                acc[2][q] = fma2(a2, hs, acc[2][q]);
                acc[3][q] = fma2(a3, hs, acc[3][q]);
            }
        }
        __syncthreads();
    }
    // --- write partials: 8 consecutive v per thread, per c ---
    #pragma unroll
    for (int q = 0; q < 4; q++) {
        int c = cb + q;
        float4 r0, r1;
        upk2(acc[0][q], r0.x, r0.y);
        upk2(acc[1][q], r0.z, r0.w);
        upk2(acc[2][q], r1.x, r1.y);
        upk2(acc[3][q], r1.z, r1.w);
        float* dst = &g_u[sp][((size_t)b * Ee + c) * Nn + v0 + v0l];
        *(float4*)(dst + 0) = r0;
        *(float4*)(dst + 4) = r1;
    }
}

// h_out = alpha*x + (1-alpha) * (sum_partials + h_prev) / den
__global__ void hop_combine(const float* __restrict__ hprev, float* __restrict__ hout,
                            const float* __restrict__ den, int denB) {
    int i = blockIdx.x * 256 + threadIdx.x;
    if (i >= NEL) return;
    int v = i & (Nn - 1);
    int b = i / (Ee * Nn);
    float s = g_u[0][i] + g_u[1][i] + g_u[2][i] + g_u[3][i] + hprev[i];
    float hn = s / den[denB * b + v];
    hout[i] = ALPHA * g_x[i] + (1.0f - ALPHA) * hn;
}

// ---------------- generic 1x1 conv (channel-mix GEMM), f32x2 packed ----------
// out[b,m,n] (+)= sum_c W[m,c]*in[c,(b,n)] + bias[m]
__global__ void conv1x1_k(Srcs srcs, int inBStride,
                          const float* __restrict__ W, const float* __restrict__ bias,
                          int M, int K, float* __restrict__ out, int outBStride, int accFlag) {
    __shared__ float Ws[16 * 68];
    __shared__ float Ins[16 * 68];
    const int tid = threadIdx.x;
    const int tx = tid & 15, ty = tid >> 4;
    const int col0 = blockIdx.x * 64;
    const int b = col0 / Nn, n0 = col0 % Nn;
    const int m0 = blockIdx.y * 64;

    u64 accP[4][2] = {};                   // [m][n-pair]

    for (int k0 = 0; k0 < K; k0 += 16) {
        for (int t = tid; t < 1024; t += 256) {
            int m = t >> 4, kk = t & 15;
            Ws[kk * 68 + m] = (m0 + m < M) ? W[(size_t)(m0 + m) * K + k0 + kk] : 0.f;
        }
        for (int t = tid; t < 1024; t += 256) {
            int kk = t >> 6, n = t & 63;
            int c = k0 + kk;
            Ins[kk * 68 + n] = srcs.p[c >> 5][(size_t)b * inBStride + (size_t)(c & 31) * Nn + n0 + n];
        }
        __syncthreads();
        #pragma unroll
        for (int kk = 0; kk < 16; kk++) {
            float4 wv = *(const float4*)&Ws[kk * 68 + ty * 4];
            u64 ip0 = *(const u64*)&Ins[kk * 68 + tx * 4];
            u64 ip1 = *(const u64*)&Ins[kk * 68 + tx * 4 + 2];
            float wa[4] = {wv.x, wv.y, wv.z, wv.w};
            #pragma unroll
            for (int u = 0; u < 4; u++) {
                u64 wp = splat2(wa[u]);
                accP[u][0] = fma2(wp, ip0, accP[u][0]);
                accP[u][1] = fma2(wp, ip1, accP[u][1]);
            }
        }
        __syncthreads();
    }
    #pragma unroll
    for (int u = 0; u < 4; u++) {
        int m = m0 + ty * 4 + u;
        if (m >= M) break;
        float bm = bias[m];
        float4 r;
        upk2(accP[u][0], r.x, r.y);
        upk2(accP[u][1], r.z, r.w);
        r.x += bm; r.y += bm; r.z += bm; r.w += bm;
        float* dst = &out[(size_t)b * outBStride + (size_t)m * Nn + n0 + tx * 4];
        if (accFlag) {
            float4 o = *(float4*)dst;
            r.x += o.x; r.y += o.y; r.z += o.z; r.w += o.w;
        }
        *(float4*)dst = r;
    }
}

// ---------------- gated TCN unit: tanh(Wf in + bf) * sigmoid(Wg in + bg) ------
__global__ void gated_conv_k(Srcs srcs, int inBStride,
                             const float* __restrict__ Wf, const float* __restrict__ bf,
                             const float* __restrict__ Wg, const float* __restrict__ bg,
                             float* __restrict__ out) {
    __shared__ float Wfs[16 * 68];
    __shared__ float Wgs[16 * 68];
    __shared__ float Ins[16 * 68];
    const int tid = threadIdx.x;
    const int tx = tid & 15, ty = tid >> 4;
    const int col0 = blockIdx.x * 64;
    const int b = col0 / Nn, n0 = col0 % Nn;
    const int m0 = blockIdx.y * 64;

    u64 accF[4][2] = {};
    u64 accG[4][2] = {};

    for (int k0 = 0; k0 < Hc; k0 += 16) {
        for (int t = tid; t < 1024; t += 256) {
            int m = t >> 4, kk = t & 15;
            Wfs[kk * 68 + m] = Wf[(size_t)(m0 + m) * Hc + k0 + kk];
            Wgs[kk * 68 + m] = Wg[(size_t)(m0 + m) * Hc + k0 + kk];
        }
        for (int t = tid; t < 1024; t += 256) {
            int kk = t >> 6, n = t & 63;
            int c = k0 + kk;
            Ins[kk * 68 + n] = srcs.p[c >> 5][(size_t)b * inBStride + (size_t)(c & 31) * Nn + n0 + n];
        }
        __syncthreads();
        #pragma unroll
        for (int kk = 0; kk < 16; kk++) {
            float4 fv = *(const float4*)&Wfs[kk * 68 + ty * 4];
            float4 gv = *(const float4*)&Wgs[kk * 68 + ty * 4];
            u64 ip0 = *(const u64*)&Ins[kk * 68 + tx * 4];
            u64 ip1 = *(const u64*)&Ins[kk * 68 + tx * 4 + 2];
            float fa[4] = {fv.x, fv.y, fv.z, fv.w};
            float ga[4] = {gv.x, gv.y, gv.z, gv.w};
            #pragma unroll
            for (int u = 0; u < 4; u++) {
                u64 fp = splat2(fa[u]);
                u64 gp = splat2(ga[u]);
                accF[u][0] = fma2(fp, ip0, accF[u][0]);
                accF[u][1] = fma2(fp, ip1, accF[u][1]);
                accG[u][0] = fma2(gp, ip0, accG[u][0]);
                accG[u][1] = fma2(gp, ip1, accG[u][1]);
            }
        }
        __syncthreads();
    }
    #pragma unroll
    for (int u = 0; u < 4; u++) {
        int m = m0 + ty * 4 + u;
        float bfm = bf[m], bgm = bg[m];
        float ff[4], gg[4];
        upk2(accF[u][0], ff[0], ff[1]);
        upk2(accF[u][1], ff[2], ff[3]);
        upk2(accG[u][0], gg[0], gg[1]);
        upk2(accG[u][1], gg[2], gg[3]);
        float4 r;
        float f, s;
        f = tanhf(ff[0] + bfm); s = 1.f / (1.f + expf(-(gg[0] + bgm))); r.x = f * s;
        f = tanhf(ff[1] + bfm); s = 1.f / (1.f + expf(-(gg[1] + bgm))); r.y = f * s;
        f = tanhf(ff[2] + bfm); s = 1.f / (1.f + expf(-(gg[2] + bgm))); r.z = f * s;
        f = tanhf(ff[3] + bfm); s = 1.f / (1.f + expf(-(gg[3] + bgm))); r.w = f * s;
        *(float4*)&out[(size_t)b * Hc * Nn + (size_t)m * Nn + n0 + tx * 4] = r;
    }
}

// ---------------- layernorm ----------------
__global__ void ln_stats_k() {
    int b = blockIdx.x;
    const float* xp = g_xacc + (size_t)b * Ee * Nn;
    float s = 0.f, s2 = 0.f;
    for (int i = threadIdx.x; i < Ee * Nn; i += blockDim.x) {
        float v = xp[i];
        s += v; s2 += v * v;
    }
    float ts = blockReduceSum(s);
    float ts2 = blockReduceSum(s2);
    if (threadIdx.x == 0) {
        float inv = 1.0f / (Ee * Nn);
        float mu = ts * inv;
        g_stats[b * 2] = mu;
        g_stats[b * 2 + 1] = ts2 * inv - mu * mu;
    }
}

__global__ void ln_apply_k(const float* __restrict__ w, const float* __restrict__ bparm) {
    int i = blockIdx.x * 256 + threadIdx.x;
    if (i >= NEL) return;
    int b = i / (Ee * Nn);
    int cn = i % (Ee * Nn);
    float mu = g_stats[b * 2];
    float var = g_stats[b * 2 + 1];
    float val = (g_xacc[i] - mu) * rsqrtf(var + EPSV) * w[cn] + bparm[cn];
    g_x[i] = fmaxf(val, 0.f);
}

// ---------------- host orchestration ----------------
extern "C" void kernel_launch(void* const* d_in, const int* in_sizes, int n_in,
                              void* d_out, int out_size) {
    (void)in_sizes; (void)n_in; (void)out_size;
    const float* in_x  = (const float*)d_in[0];
    const float* dyG   = (const float*)d_in[1];
    const float* stG   = (const float*)d_in[2];
    const float* spE   = (const float*)d_in[3];
    const float* tdE   = (const float*)d_in[4];
    const float* twE   = (const float*)d_in[5];
    const float* encWf = (const float*)d_in[6];
    const float* encbf = (const float*)d_in[7];
    const float* encWg = (const float*)d_in[8];
    const float* encbg = (const float*)d_in[9];
    const float* skW   = (const float*)d_in[10];
    const float* skb   = (const float*)d_in[11];
    const float* nw    = (const float*)d_in[12];
    const float* nb    = (const float*)d_in[13];
    const float* gW[3] = {(const float*)d_in[14], (const float*)d_in[16], (const float*)d_in[18]};
    const float* gb[3] = {(const float*)d_in[15], (const float*)d_in[17], (const float*)d_in[19]};
    const float* seW   = (const float*)d_in[20];
    const float* seb   = (const float*)d_in[21];
    const float* eW    = (const float*)d_in[22];
    const float* eb    = (const float*)d_in[23];
    float* outp = (float*)d_out;

    float *px, *pxacc, *ph1, *ph2, *phid, *phid2, *pskip, *prss, *prsd, *pcsd;
    cudaGetSymbolAddress((void**)&px,    g_x);
    cudaGetSymbolAddress((void**)&pxacc, g_xacc);
    cudaGetSymbolAddress((void**)&ph1,   g_h1);
    cudaGetSymbolAddress((void**)&ph2,   g_h2);
    cudaGetSymbolAddress((void**)&phid,  g_hid);
    cudaGetSymbolAddress((void**)&phid2, g_hid2);
    cudaGetSymbolAddress((void**)&pskip, g_skip);
    cudaGetSymbolAddress((void**)&prss,  g_rs_s);
    cudaGetSymbolAddress((void**)&prsd,  g_rs_d);
    cudaGetSymbolAddress((void**)&pcsd,  g_cs_d);

    // x <- input; degree sums (input-only, deterministic each call)
    copyk<<<NEL / 256, 256>>>(px, in_x, NEL);
    rowsum_static<<<Nn, 256>>>(stG);
    rowsum_dy<<<dim3(Nn, Bb), 256>>>(dyG);
    colsum_dy<<<dim3(Nn / 256, Bb, CRS), 256>>>(dyG);
    colsum_fin<<<Bb * Nn / 256, 256>>>();

    const dim3 convGrid(Bb * Nn / 64, 1);
    for (int i = 0; i < 3; i++) {
        // ---- TCN chain ----
        Srcs s1; s1.p[0] = px; s1.p[1] = spE; s1.p[2] = tdE; s1.p[3] = twE;
        gated_conv_k<<<dim3(Bb * Nn / 64, 2), 256>>>(s1, Ee * Nn,
            encWf + (size_t)(i * 2 + 0) * Hc * Hc, encbf + (i * 2 + 0) * Hc,
            encWg + (size_t)(i * 2 + 0) * Hc * Hc, encbg + (i * 2 + 0) * Hc, phid);
        Srcs s2; for (int s = 0; s < 4; s++) s2.p[s] = phid + (size_t)s * 32 * Nn;
        gated_conv_k<<<dim3(Bb * Nn / 64, 2), 256>>>(s2, Hc * Nn,
            encWf + (size_t)(i * 2 + 1) * Hc * Hc, encbf + (i * 2 + 1) * Hc,
            encWg + (size_t)(i * 2 + 1) * Hc * Hc, encbg + (i * 2 + 1) * Hc, phid2);
        // ---- skip += skip_W @ hidden ----
        Srcs s3; for (int s = 0; s < 4; s++) s3.p[s] = phid2 + (size_t)s * 32 * Nn;
        conv1x1_k<<<dim3(Bb * Nn / 64, 4), 256>>>(s3, Hc * Nn,
            skW + (size_t)i * Sc * Hc, skb + i * Sc, Sc, Hc, pskip, Sc * Nn, i > 0);
        // ---- mixprops: xacc starts at residual, each mlp accumulates ----
        copyk<<<NEL / 256, 256>>>(pxacc, px, NEL);
        for (int g = 0; g < 3; g++) {
            const float* A = (g == 0) ? stG : dyG;
            size_t abst = (g == 0) ? 0 : (size_t)Nn * Nn;
            const float* den = (g == 0) ? prss : (g == 1 ? prsd : pcsd);
            int denB = (g == 0) ? 0 : Nn;
            bool tr = (g == 2);
            // hop 1
            if (tr) spmm_k<true ><<<dim3(16, Bb, SPLIT), 128>>>(A, abst, px);
            else    spmm_k<false><<<dim3(16, Bb, SPLIT), 128>>>(A, abst, px);
            hop_combine<<<NEL / 256, 256>>>(px, ph1, den, denB);
            // hop 2
            if (tr) spmm_k<true ><<<dim3(16, Bb, SPLIT), 128>>>(A, abst, ph1);
            else    spmm_k<false><<<dim3(16, Bb, SPLIT), 128>>>(A, abst, ph1);
            hop_combine<<<NEL / 256, 256>>>(ph1, ph2, den, denB);
            // mlp on concat [x, h1, h2] -> accumulate into xacc
            Srcs sm; sm.p[0] = px; sm.p[1] = ph1; sm.p[2] = ph2;
            conv1x1_k<<<convGrid, 256>>>(sm, Ee * Nn,
                gW[g] + (size_t)i * Ee * 96, gb[g] + i * Ee, Ee, 96, pxacc, Ee * Nn, 1);
        }
        // ---- layernorm + relu -> new x ----
        ln_stats_k<<<Bb, 1024>>>();
        ln_apply_k<<<NEL / 256, 256>>>(nw + (size_t)i * Ee * Nn, nb + (size_t)i * Ee * Nn);
    }
    // ---- skip end + output ----
    Srcs se; se.p[0] = px;
    conv1x1_k<<<dim3(Bb * Nn / 64, 4), 256>>>(se, Ee * Nn, seW, seb, Sc, Ee, pskip, Sc * Nn, 1);
    Srcs send; for (int s = 0; s < 8; s++) send.p[s] = pskip + (size_t)s * 32 * Nn;
    conv1x1_k<<<convGrid, 256>>>(send, Sc * Nn, eW, eb, Tt, Sc, outp, Tt * Nn, 0);
}